// round 7
// baseline (speedup 1.0000x reference)
#include <cuda_runtime.h>
#include <cuda_bf16.h>
#include <math.h>
#include <stdint.h>

#define Bsz 8
#define Nn  1024
#define Dd  512
#define Hh  8
#define HD  64
#define Mrows (Bsz*Nn)

// ---------------- scratch (device globals) ----------------
__device__ uint32_t g_xhi[Mrows*256], g_xlo[Mrows*256];        // X split  [row][256]
__device__ uint32_t g_whi[4*512*256], g_wlo[4*512*256];        // 4 weights [w][row][256] (Wq|Wk|Wv|Wo)
__device__ uint32_t g_qhi[Mrows*32*Hh], g_qlo[Mrows*32*Hh];    // [B,H,N][32]
__device__ uint32_t g_khi[Mrows*32*Hh], g_klo[Mrows*32*Hh];
__device__ uint32_t g_vhi[Mrows*32*Hh], g_vlo[Mrows*32*Hh];
__device__ uint32_t g_athi[Mrows*256], g_atlo[Mrows*256];      // attn out split [row][256]
__device__ float    g_y[(size_t)Mrows*Dd];

// ---------------- helpers ----------------
__device__ __forceinline__ uint32_t smem_u32(const void* p) {
    uint32_t a;
    asm("{ .reg .u64 t; cvta.to.shared.u64 t, %1; cvt.u32.u64 %0, t; }" : "=r"(a) : "l"(p));
    return a;
}
__device__ __forceinline__ float ex2f(float x) {
    float r;
    asm("ex2.approx.ftz.f32 %0, %1;" : "=f"(r) : "f"(x));
    return r;
}
#define MMA_BF16(c0,c1,c2,c3, a0,a1,a2,a3, b0,b1) \
    asm volatile("mma.sync.aligned.m16n8k16.row.col.f32.bf16.bf16.f32 " \
        "{%0,%1,%2,%3},{%4,%5,%6,%7},{%8,%9},{%0,%1,%2,%3};" \
        : "+f"(c0),"+f"(c1),"+f"(c2),"+f"(c3) \
        : "r"(a0),"r"(a1),"r"(a2),"r"(a3),"r"(b0),"r"(b1))
#define LDSM_X4(r0,r1,r2,r3, a) \
    asm volatile("ldmatrix.sync.aligned.m8n8.x4.shared.b16 {%0,%1,%2,%3}, [%4];" \
        : "=r"(r0),"=r"(r1),"=r"(r2),"=r"(r3) : "r"(a))
#define LDSM_X4_T(r0,r1,r2,r3, a) \
    asm volatile("ldmatrix.sync.aligned.m8n8.x4.trans.shared.b16 {%0,%1,%2,%3}, [%4];" \
        : "=r"(r0),"=r"(r1),"=r"(r2),"=r"(r3) : "r"(a))

__device__ __forceinline__ uint32_t pack_hi(float x, float y) {
    __nv_bfloat162 p;
    p.x = __float2bfloat16(x);
    p.y = __float2bfloat16(y);
    return *(uint32_t*)&p;
}
__device__ __forceinline__ uint32_t pack_lo(float x, float y) {
    __nv_bfloat16 hx = __float2bfloat16(x);
    __nv_bfloat16 hy = __float2bfloat16(y);
    __nv_bfloat162 p;
    p.x = __float2bfloat16(x - __bfloat162float(hx));
    p.y = __float2bfloat16(y - __bfloat162float(hy));
    return *(uint32_t*)&p;
}

// ---------------- split converts ----------------
__global__ __launch_bounds__(256) void split_kernel(
    const float* __restrict__ in, uint32_t* __restrict__ hi,
    uint32_t* __restrict__ lo, int n4)
{
    int i = blockIdx.x * 256 + threadIdx.x;
    if (i < n4) {
        float4 v = ((const float4*)in)[i];
        uint2 h, l;
        h.x = pack_hi(v.x, v.y); h.y = pack_hi(v.z, v.w);
        l.x = pack_lo(v.x, v.y); l.y = pack_lo(v.z, v.w);
        ((uint2*)hi)[i] = h;
        ((uint2*)lo)[i] = l;
    }
}

__global__ __launch_bounds__(256) void split4_kernel(
    const float* __restrict__ w0, const float* __restrict__ w1,
    const float* __restrict__ w2, const float* __restrict__ w3,
    uint32_t* __restrict__ hi, uint32_t* __restrict__ lo)
{
    const int wsel = blockIdx.y;
    const float* in = (wsel == 0) ? w0 : (wsel == 1) ? w1 : (wsel == 2) ? w2 : w3;
    const int i = blockIdx.x * 256 + threadIdx.x;
    const size_t off = (size_t)wsel * 512 * 256;
    float4 v = ((const float4*)in)[i];
    uint2 h, l;
    h.x = pack_hi(v.x, v.y); h.y = pack_hi(v.z, v.w);
    l.x = pack_lo(v.x, v.y); l.y = pack_lo(v.z, v.w);
    ((uint2*)(hi + off))[i] = h;
    ((uint2*)(lo + off))[i] = l;
}

// ===========================================================================
// Shared GEMM machinery: CTA 128x128, 8 warps (2x4), K-stage 64, dbl-buffered,
// ldmatrix fragment loads, 3-pass bf16-split mma.
// ===========================================================================
#define APAD2 36
#define TILE_U32 (128*APAD2)
#define TILE_B   (TILE_U32*4)
#define GEMM_SMEM (2*4*TILE_B)    // 147456 bytes

__device__ __forceinline__ void gfill(
    uint32_t* smu, int stage,
    const uint32_t* __restrict__ Ahi, const uint32_t* __restrict__ Alo,
    const uint32_t* __restrict__ Bhi, const uint32_t* __restrict__ Blo,
    int row0, int col0, int k0u, int t)
{
    const int r = t >> 1, c0 = (t & 1) * 16;
    uint32_t* d = smu + stage * 4 * TILE_U32;
    const uint32_t* s0 = Ahi + (size_t)(row0 + r) * 256 + k0u + c0;
    const uint32_t* s1 = Alo + (size_t)(row0 + r) * 256 + k0u + c0;
    const uint32_t* s2 = Bhi + (size_t)(col0 + r) * 256 + k0u + c0;
    const uint32_t* s3 = Blo + (size_t)(col0 + r) * 256 + k0u + c0;
    uint32_t* dd = d + r * APAD2 + c0;
#pragma unroll
    for (int u = 0; u < 4; u++) {
        ((uint4*)(dd             ))[u] = ((const uint4*)s0)[u];
        ((uint4*)(dd + TILE_U32  ))[u] = ((const uint4*)s1)[u];
        ((uint4*)(dd + 2*TILE_U32))[u] = ((const uint4*)s2)[u];
        ((uint4*)(dd + 3*TILE_U32))[u] = ((const uint4*)s3)[u];
    }
}

// mainloop: accumulates acc[4][4][4] for this thread's warp tile.
__device__ __forceinline__ void gemm_mainloop(
    uint32_t* smu, uint32_t smb,
    const uint32_t* __restrict__ Ahi, const uint32_t* __restrict__ Alo,
    const uint32_t* __restrict__ Bhi, const uint32_t* __restrict__ Blo,
    int row0, int col0, int t, float acc[4][4][4])
{
    const int lane = t & 31, wid = t >> 5;
    const int wm = wid & 1, wn = wid >> 1;
    // ldmatrix per-lane offset (bytes): groups of 8 lanes -> the 4 8x8 matrices
    const int lfoff = (((lane & 7) + ((lane >> 3) & 1) * 8) * 36 + (lane >> 4) * 4) * 4;

    gfill(smu, 0, Ahi, Alo, Bhi, Blo, row0, col0, 0, t);
    __syncthreads();

    for (int kt = 0; kt < 8; kt++) {
        if (kt < 7) gfill(smu, (kt + 1) & 1, Ahi, Alo, Bhi, Blo, row0, col0, (kt + 1) * 32, t);

        const uint32_t sb  = smb + (uint32_t)((kt & 1) * 4 * TILE_B);
        const uint32_t sbA = sb + (uint32_t)(wm * 64) * 144 + lfoff;
        const uint32_t sbB = sb + 2u*TILE_B + (uint32_t)(wn * 32) * 144 + lfoff;

#pragma unroll
        for (int ks = 0; ks < 4; ks++) {
            const uint32_t kb4 = ks * 32;   // bytes
            uint32_t ah[4][4], al[4][4], bh[4][2], bl[4][2];
#pragma unroll
            for (int mt = 0; mt < 4; mt++) {
                const uint32_t aA = sbA + mt * (16*144) + kb4;
                LDSM_X4(ah[mt][0], ah[mt][1], ah[mt][2], ah[mt][3], aA);
                LDSM_X4(al[mt][0], al[mt][1], al[mt][2], al[mt][3], aA + TILE_B);
            }
#pragma unroll
            for (int np = 0; np < 2; np++) {
                const uint32_t aB = sbB + np * (16*144) + kb4;
                LDSM_X4(bh[2*np][0], bh[2*np+1][0], bh[2*np][1], bh[2*np+1][1], aB);
                LDSM_X4(bl[2*np][0], bl[2*np+1][0], bl[2*np][1], bl[2*np+1][1], aB + TILE_B);
            }
#pragma unroll
            for (int mt = 0; mt < 4; mt++)
#pragma unroll
                for (int nt = 0; nt < 4; nt++) {
                    MMA_BF16(acc[mt][nt][0],acc[mt][nt][1],acc[mt][nt][2],acc[mt][nt][3],
                             ah[mt][0],ah[mt][1],ah[mt][2],ah[mt][3], bh[nt][0],bh[nt][1]);
                    MMA_BF16(acc[mt][nt][0],acc[mt][nt][1],acc[mt][nt][2],acc[mt][nt][3],
                             ah[mt][0],ah[mt][1],ah[mt][2],ah[mt][3], bl[nt][0],bl[nt][1]);
                    MMA_BF16(acc[mt][nt][0],acc[mt][nt][1],acc[mt][nt][2],acc[mt][nt][3],
                             al[mt][0],al[mt][1],al[mt][2],al[mt][3], bh[nt][0],bh[nt][1]);
                }
        }
        __syncthreads();
    }
}

// ---- fused QKV projection: grid (64, 12); cols 0..1535 over Wq|Wk|Wv ----
__global__ __launch_bounds__(256, 1) void gemm_qkv(
    const float* __restrict__ bq, const float* __restrict__ bk,
    const float* __restrict__ bv)
{
    extern __shared__ uint32_t smu[];
    const uint32_t smb = smem_u32(smu);
    const int t = threadIdx.x;
    const int lane = t & 31, wid = t >> 5;
    const int row0 = blockIdx.x * 128, col0 = blockIdx.y * 128;
    const int wm = wid & 1, wn = wid >> 1;
    const int g = lane >> 2, tig = lane & 3;

    float acc[4][4][4];
#pragma unroll
    for (int mt = 0; mt < 4; mt++)
#pragma unroll
        for (int nt = 0; nt < 4; nt++)
#pragma unroll
            for (int e = 0; e < 4; e++) acc[mt][nt][e] = 0.f;

    gemm_mainloop(smu, smb, g_xhi, g_xlo, g_whi, g_wlo, row0, col0, t, acc);

    const int w = blockIdx.y >> 2;                 // 0:q 1:k 2:v (128 | 512)
    const float* bias = (w == 0) ? bq : (w == 1) ? bk : bv;
    uint32_t* oh = (w == 0) ? g_qhi : (w == 1) ? g_khi : g_vhi;
    uint32_t* ol = (w == 0) ? g_qlo : (w == 1) ? g_klo : g_vlo;

#pragma unroll
    for (int mt = 0; mt < 4; mt++) {
#pragma unroll
        for (int nt = 0; nt < 4; nt++) {
            const int gc = col0 + wn*32 + nt*8 + tig*2;
            const int lc = gc & 511;
            const float b0 = bias[lc], b1 = bias[lc+1];
            const int h = lc >> 6, ucol = (lc >> 1) & 31;
            const int ra = row0 + wm*64 + mt*16 + g;
            const int rb = ra + 8;
            {
                const int bi = ra >> 10, ni = ra & 1023;
                const float x = acc[mt][nt][0] + b0, y = acc[mt][nt][1] + b1;
                const size_t o = ((size_t)(bi*Hh + h)*Nn + ni)*32 + ucol;
                oh[o] = pack_hi(x, y);  ol[o] = pack_lo(x, y);
            }
            {
                const int bi = rb >> 10, ni = rb & 1023;
                const float x = acc[mt][nt][2] + b0, y = acc[mt][nt][3] + b1;
                const size_t o = ((size_t)(bi*Hh + h)*Nn + ni)*32 + ucol;
                oh[o] = pack_hi(x, y);  ol[o] = pack_lo(x, y);
            }
        }
    }
}

// ---- output projection + residual: grid (64, 4) ----
__global__ __launch_bounds__(256, 1) void gemm_out(
    const float* __restrict__ bo, const float* __restrict__ resid)
{
    extern __shared__ uint32_t smu[];
    const uint32_t smb = smem_u32(smu);
    const int t = threadIdx.x;
    const int lane = t & 31, wid = t >> 5;
    const int row0 = blockIdx.x * 128, col0 = blockIdx.y * 128;
    const int wm = wid & 1, wn = wid >> 1;
    const int g = lane >> 2, tig = lane & 3;

    float acc[4][4][4];
#pragma unroll
    for (int mt = 0; mt < 4; mt++)
#pragma unroll
        for (int nt = 0; nt < 4; nt++)
#pragma unroll
            for (int e = 0; e < 4; e++) acc[mt][nt][e] = 0.f;

    gemm_mainloop(smu, smb, g_athi, g_atlo,
                  g_whi + 3*512*256, g_wlo + 3*512*256, row0, col0, t, acc);

#pragma unroll
    for (int mt = 0; mt < 4; mt++) {
#pragma unroll
        for (int nt = 0; nt < 4; nt++) {
            const int gc = col0 + wn*32 + nt*8 + tig*2;
            const float b0 = bo[gc], b1 = bo[gc+1];
            const int ra = row0 + wm*64 + mt*16 + g;
            const int rb = ra + 8;
            {
                const size_t off = (size_t)ra * Dd + gc;
                float2 x = *(const float2*)(resid + off);
                float2 r; r.x = acc[mt][nt][0] + b0 + x.x; r.y = acc[mt][nt][1] + b1 + x.y;
                *(float2*)(g_y + off) = r;
            }
            {
                const size_t off = (size_t)rb * Dd + gc;
                float2 x = *(const float2*)(resid + off);
                float2 r; r.x = acc[mt][nt][2] + b0 + x.x; r.y = acc[mt][nt][3] + b1 + x.y;
                *(float2*)(g_y + off) = r;
            }
        }
    }
}

// ===========================================================================
// Tensor-core flash attention, fixed-max softmax (unchanged from R6).
// ===========================================================================
#define ASTRIDE 144
#define AT_TILE_U32 (128*36)
#define ATTN_SMEM (4*AT_TILE_U32*4)    // 73728 bytes

__global__ __launch_bounds__(256, 1) void attn_kernel(const float* __restrict__ adj)
{
    extern __shared__ uint32_t smu[];
    const uint32_t smb = smem_u32(smu);
    const int t = threadIdx.x;
    const int lane = t & 31, wid = t >> 5;
    const int g = lane >> 2, tig = lane & 3;
    const int lm = lane >> 3, lr8 = lane & 7;
    const int q0 = blockIdx.x * 128;
    const int h  = blockIdx.y;
    const int b  = blockIdx.z;

    const size_t hbase = (size_t)(b*Hh + h) * Nn * 32;
    const uint32_t* Qhi = g_qhi + hbase;
    const uint32_t* Qlo = g_qlo + hbase;
    const uint32_t* Khi = g_khi + hbase;
    const uint32_t* Klo = g_klo + hbase;
    const uint32_t* Vhi = g_vhi + hbase;
    const uint32_t* Vlo = g_vlo + hbase;

    const uint32_t smbKhi = smb;
    const uint32_t smbKlo = smb + 1*AT_TILE_U32*4;
    const uint32_t smbVhi = smb + 2*AT_TILE_U32*4;
    const uint32_t smbVlo = smb + 3*AT_TILE_U32*4;

    const int lofK = ((lm >> 1)*8 + lr8) * ASTRIDE + (lm & 1) * 16;
    const int lofV = ((lm & 1)*8 + lr8) * ASTRIDE + (lm >> 1) * 16;

    const int rq  = q0 + wid*16 + g;
    const int rq8 = rq + 8;
    uint32_t qh[4][4], ql[4][4];
#pragma unroll
    for (int ks = 0; ks < 4; ks++) {
        const int c = ks*8 + tig;
        qh[ks][0] = Qhi[(size_t)rq *32 + c];     qh[ks][1] = Qhi[(size_t)rq8*32 + c];
        qh[ks][2] = Qhi[(size_t)rq *32 + c + 4]; qh[ks][3] = Qhi[(size_t)rq8*32 + c + 4];
        ql[ks][0] = Qlo[(size_t)rq *32 + c];     ql[ks][1] = Qlo[(size_t)rq8*32 + c];
        ql[ks][2] = Qlo[(size_t)rq *32 + c + 4]; ql[ks][3] = Qlo[(size_t)rq8*32 + c + 4];
    }

    float o[8][4];
#pragma unroll
    for (int i = 0; i < 8; i++)
#pragma unroll
        for (int e = 0; e < 4; e++) o[i][e] = 0.f;
    float l0 = 0.f, l1 = 0.f;
    const float C = 0.125f * 1.44269504088896f;

    const int fr = t >> 1, fc = (t & 1) * 16;

    for (int kt = 0; kt < 8; kt++) {
        const int k0 = kt * 128;
        __syncthreads();
        {
            const size_t gsrc = (size_t)(k0 + fr) * 32 + fc;
            uint32_t* d = smu + fr*36 + fc;
#pragma unroll
            for (int u = 0; u < 4; u++) {
                ((uint4*)(d                ))[u] = ((const uint4*)(Khi + gsrc))[u];
                ((uint4*)(d +   AT_TILE_U32))[u] = ((const uint4*)(Klo + gsrc))[u];
                ((uint4*)(d + 2*AT_TILE_U32))[u] = ((const uint4*)(Vhi + gsrc))[u];
                ((uint4*)(d + 3*AT_TILE_U32))[u] = ((const uint4*)(Vlo + gsrc))[u];
            }
        }
        __syncthreads();

        float sc[16][4];
#pragma unroll
        for (int i = 0; i < 16; i++)
#pragma unroll
            for (int e = 0; e < 4; e++) sc[i][e] = 0.f;

#pragma unroll
        for (int ks = 0; ks < 4; ks++) {
#pragma unroll
            for (int nfp = 0; nfp < 8; nfp++) {
                uint32_t kh0,kh1,kh2,kh3, kl0,kl1,kl2,kl3;
                const uint32_t aK = lofK + nfp*2304 + ks*32;
                LDSM_X4(kh0,kh1,kh2,kh3, smbKhi + aK);
                LDSM_X4(kl0,kl1,kl2,kl3, smbKlo + aK);
                float* s0 = sc[2*nfp];
                float* s1 = sc[2*nfp+1];
                MMA_BF16(s0[0],s0[1],s0[2],s0[3], qh[ks][0],qh[ks][1],qh[ks][2],qh[ks][3], kh0,kh1);
                MMA_BF16(s0[0],s0[1],s0[2],s0[3], qh[ks][0],qh[ks][1],qh[ks][2],qh[ks][3], kl0,kl1);
                MMA_BF16(s0[0],s0[1],s0[2],s0[3], ql[ks][0],ql[ks][1],ql[ks][2],ql[ks][3], kh0,kh1);
                MMA_BF16(s1[0],s1[1],s1[2],s1[3], qh[ks][0],qh[ks][1],qh[ks][2],qh[ks][3], kh2,kh3);
                MMA_BF16(s1[0],s1[1],s1[2],s1[3], qh[ks][0],qh[ks][1],qh[ks][2],qh[ks][3], kl2,kl3);
                MMA_BF16(s1[0],s1[1],s1[2],s1[3], ql[ks][0],ql[ks][1],ql[ks][2],ql[ks][3], kh2,kh3);
            }
        }

        const float* arow0 = adj + ((size_t)b*Nn + rq )*Nn + k0 + 2*tig;
        const float* arow1 = adj + ((size_t)b*Nn + rq8)*Nn + k0 + 2*tig;
        float ps0 = 0.f, ps1 = 0.f;
#pragma unroll
        for (int nf = 0; nf < 16; nf++) {
            float2 a0 = *(const float2*)(arow0 + nf*8);
            float2 a1 = *(const float2*)(arow1 + nf*8);
            sc[nf][0] = ex2f(sc[nf][0] * C * a0.x);
            sc[nf][1] = ex2f(sc[nf][1] * C * a0.y);
            sc[nf][2] = ex2f(sc[nf][2] * C * a1.x);
            sc[nf][3] = ex2f(sc[nf][3] * C * a1.y);
            ps0 += sc[nf][0] + sc[nf][1];
            ps1 += sc[nf][2] + sc[nf][3];
        }
        l0 += ps0;
        l1 += ps1;

#pragma unroll
        for (int j = 0; j < 8; j++) {
            const uint32_t ph0 = pack_hi(sc[2*j  ][0], sc[2*j  ][1]);
            const uint32_t ph1 = pack_hi(sc[2*j  ][2], sc[2*j  ][3]);
            const uint32_t ph2 = pack_hi(sc[2*j+1][0], sc[2*j+1][1]);
            const uint32_t ph3 = pack_hi(sc[2*j+1][2], sc[2*j+1][3]);
            const uint32_t pl0 = pack_lo(sc[2*j  ][0], sc[2*j  ][1]);
            const uint32_t pl1 = pack_lo(sc[2*j  ][2], sc[2*j  ][3]);
            const uint32_t pl2 = pack_lo(sc[2*j+1][0], sc[2*j+1][1]);
            const uint32_t pl3 = pack_lo(sc[2*j+1][2], sc[2*j+1][3]);
#pragma unroll
            for (int vx = 0; vx < 4; vx++) {
                uint32_t vh0,vh1,vh2,vh3, vl0,vl1,vl2,vl3;
                const uint32_t aV = lofV + j*2304 + vx*32;
                LDSM_X4_T(vh0,vh1,vh2,vh3, smbVhi + aV);
                LDSM_X4_T(vl0,vl1,vl2,vl3, smbVlo + aV);
                float* o0 = o[2*vx];
                float* o1 = o[2*vx+1];
                MMA_BF16(o0[0],o0[1],o0[2],o0[3], ph0,ph1,ph2,ph3, vh0,vh1);
                MMA_BF16(o0[0],o0[1],o0[2],o0[3], ph0,ph1,ph2,ph3, vl0,vl1);
                MMA_BF16(o0[0],o0[1],o0[2],o0[3], pl0,pl1,pl2,pl3, vh0,vh1);
                MMA_BF16(o1[0],o1[1],o1[2],o1[3], ph0,ph1,ph2,ph3, vh2,vh3);
                MMA_BF16(o1[0],o1[1],o1[2],o1[3], ph0,ph1,ph2,ph3, vl2,vl3);
                MMA_BF16(o1[0],o1[1],o1[2],o1[3], pl0,pl1,pl2,pl3, vh2,vh3);
            }
        }
    }

    l0 += __shfl_xor_sync(0xffffffffu, l0, 1, 4);
    l0 += __shfl_xor_sync(0xffffffffu, l0, 2, 4);
    l1 += __shfl_xor_sync(0xffffffffu, l1, 1, 4);
    l1 += __shfl_xor_sync(0xffffffffu, l1, 2, 4);

    const float i0 = 1.0f / l0, i1 = 1.0f / l1;
    const size_t gr  = (size_t)b*Nn + rq;
    const size_t gr8 = (size_t)b*Nn + rq8;
#pragma unroll
    for (int dnf = 0; dnf < 8; dnf++) {
        const int ucol = h*32 + dnf*4 + tig;
        {
            const float x = o[dnf][0]*i0, y = o[dnf][1]*i0;
            g_athi[gr*256 + ucol] = pack_hi(x, y);
            g_atlo[gr*256 + ucol] = pack_lo(x, y);
        }
        {
            const float x = o[dnf][2]*i1, y = o[dnf][3]*i1;
            g_athi[gr8*256 + ucol] = pack_hi(x, y);
            g_atlo[gr8*256 + ucol] = pack_lo(x, y);
        }
    }
}

// ---------------------------------------------------------------------------
// LayerNorm over last dim (512). One block (128 thr) per row.
// ---------------------------------------------------------------------------
__global__ __launch_bounds__(128) void ln_kernel(
    const float* __restrict__ gamma, const float* __restrict__ beta,
    float* __restrict__ out)
{
    const int row = blockIdx.x;
    const int t   = threadIdx.x;
    const float* y = g_y + (size_t)row * Dd;

    float4 v = *(const float4*)(y + t*4);
    float s  = v.x + v.y + v.z + v.w;
    float ss = v.x*v.x + v.y*v.y + v.z*v.z + v.w*v.w;
#pragma unroll
    for (int off = 16; off; off >>= 1) {
        s  += __shfl_xor_sync(0xffffffffu, s,  off);
        ss += __shfl_xor_sync(0xffffffffu, ss, off);
    }
    __shared__ float sbuf[8];
    const int w = t >> 5;
    if ((t & 31) == 0) { sbuf[w] = s; sbuf[4 + w] = ss; }
    __syncthreads();
    s  = sbuf[0] + sbuf[1] + sbuf[2] + sbuf[3];
    ss = sbuf[4] + sbuf[5] + sbuf[6] + sbuf[7];

    const float mean = s * (1.f/512.f);
    const float var  = ss * (1.f/512.f) - mean*mean;
    const float inv  = rsqrtf(var + 1e-5f);

    float4 g4 = *(const float4*)(gamma + t*4);
    float4 b4 = *(const float4*)(beta  + t*4);
    float4 r;
    r.x = (v.x - mean) * inv * g4.x + b4.x;
    r.y = (v.y - mean) * inv * g4.y + b4.y;
    r.z = (v.z - mean) * inv * g4.z + b4.z;
    r.w = (v.w - mean) * inv * g4.w + b4.w;
    *(float4*)(out + (size_t)row*Dd + t*4) = r;
}

// ---------------------------------------------------------------------------
extern "C" void kernel_launch(void* const* d_in, const int* in_sizes, int n_in,
                              void* d_out, int out_size)
{
    const float* X     = (const float*)d_in[0];
    const float* adj   = (const float*)d_in[1];
    const float* Wq    = (const float*)d_in[2];
    const float* bq    = (const float*)d_in[3];
    const float* Wk    = (const float*)d_in[4];
    const float* bk    = (const float*)d_in[5];
    const float* Wv    = (const float*)d_in[6];
    const float* bv    = (const float*)d_in[7];
    const float* Wo    = (const float*)d_in[8];
    const float* bo    = (const float*)d_in[9];
    const float* gamma = (const float*)d_in[10];
    const float* beta  = (const float*)d_in[11];

    uint32_t *xhi, *xlo, *whi, *wlo;
    cudaGetSymbolAddress((void**)&xhi, g_xhi);
    cudaGetSymbolAddress((void**)&xlo, g_xlo);
    cudaGetSymbolAddress((void**)&whi, g_whi);
    cudaGetSymbolAddress((void**)&wlo, g_wlo);

    cudaFuncSetAttribute(gemm_qkv,
                         cudaFuncAttributeMaxDynamicSharedMemorySize, GEMM_SMEM);
    cudaFuncSetAttribute(gemm_out,
                         cudaFuncAttributeMaxDynamicSharedMemorySize, GEMM_SMEM);
    cudaFuncSetAttribute(attn_kernel,
                         cudaFuncAttributeMaxDynamicSharedMemorySize, ATTN_SMEM);

    split_kernel<<<Mrows*512/4/256, 256>>>(X, xhi, xlo, Mrows*512/4);
    split4_kernel<<<dim3(256, 4), 256>>>(Wq, Wk, Wv, Wo, whi, wlo);

    gemm_qkv<<<dim3(Mrows/128, 12), 256, GEMM_SMEM>>>(bq, bk, bv);

    attn_kernel<<<dim3(Nn/128, Hh, Bsz), 256, ATTN_SMEM>>>(adj);

    gemm_out<<<dim3(Mrows/128, 4), 256, GEMM_SMEM>>>(bo, X);

    ln_kernel<<<Mrows, 128>>>(gamma, beta, (float*)d_out);
}

// round 8
// speedup vs baseline: 2.0689x; 2.0689x over previous
#include <cuda_runtime.h>
#include <cuda_fp16.h>
#include <math.h>
#include <stdint.h>

#define Bsz 8
#define Nn  1024
#define Dd  512
#define Hh  8
#define HD  64
#define Mrows (Bsz*Nn)

// ---------------- scratch (device globals) ----------------
// u32 = packed half2 (even,odd) pairs.
__device__ uint32_t g_x[Mrows*256];              // X fp16 [row][256]
__device__ uint32_t g_w[4*512*256];              // weights fp16 [w][row][256] (Wq|Wk|Wv|Wo)
__device__ uint32_t g_q[Bsz*Hh*Nn*32];           // [B,H,N][32]
__device__ uint32_t g_k[Bsz*Hh*Nn*32];
__device__ uint32_t g_v[Bsz*Hh*Nn*32];
__device__ uint32_t g_at[Mrows*256];             // attn out fp16 [row][256]
__device__ float    g_y[(size_t)Mrows*Dd];

// ---------------- helpers ----------------
__device__ __forceinline__ uint32_t smem_u32(const void* p) {
    uint32_t a;
    asm("{ .reg .u64 t; cvta.to.shared.u64 t, %1; cvt.u32.u64 %0, t; }" : "=r"(a) : "l"(p));
    return a;
}
__device__ __forceinline__ float ex2f(float x) {
    float r;
    asm("ex2.approx.ftz.f32 %0, %1;" : "=f"(r) : "f"(x));
    return r;
}
#define MMA_FP16(c0,c1,c2,c3, a0,a1,a2,a3, b0,b1) \
    asm volatile("mma.sync.aligned.m16n8k16.row.col.f32.f16.f16.f32 " \
        "{%0,%1,%2,%3},{%4,%5,%6,%7},{%8,%9},{%0,%1,%2,%3};" \
        : "+f"(c0),"+f"(c1),"+f"(c2),"+f"(c3) \
        : "r"(a0),"r"(a1),"r"(a2),"r"(a3),"r"(b0),"r"(b1))
#define LDSM_X4(r0,r1,r2,r3, a) \
    asm volatile("ldmatrix.sync.aligned.m8n8.x4.shared.b16 {%0,%1,%2,%3}, [%4];" \
        : "=r"(r0),"=r"(r1),"=r"(r2),"=r"(r3) : "r"(a))
#define LDSM_X4_T(r0,r1,r2,r3, a) \
    asm volatile("ldmatrix.sync.aligned.m8n8.x4.trans.shared.b16 {%0,%1,%2,%3}, [%4];" \
        : "=r"(r0),"=r"(r1),"=r"(r2),"=r"(r3) : "r"(a))

__device__ __forceinline__ uint32_t pack_h2(float x, float y) {
    __half2 p = __floats2half2_rn(x, y);
    return *(uint32_t*)&p;
}

// ---------------- fp32 -> fp16x2 converts ----------------
__global__ __launch_bounds__(256) void cvt_kernel(
    const float* __restrict__ in, uint32_t* __restrict__ out, int n4)
{
    int i = blockIdx.x * 256 + threadIdx.x;
    if (i < n4) {
        float4 v = ((const float4*)in)[i];
        uint2 h;
        h.x = pack_h2(v.x, v.y); h.y = pack_h2(v.z, v.w);
        ((uint2*)out)[i] = h;
    }
}

__global__ __launch_bounds__(256) void cvt4_kernel(
    const float* __restrict__ w0, const float* __restrict__ w1,
    const float* __restrict__ w2, const float* __restrict__ w3,
    uint32_t* __restrict__ out)
{
    const int wsel = blockIdx.y;
    const float* in = (wsel == 0) ? w0 : (wsel == 1) ? w1 : (wsel == 2) ? w2 : w3;
    const int i = blockIdx.x * 256 + threadIdx.x;
    const size_t off = (size_t)wsel * 512 * 256;
    float4 v = ((const float4*)in)[i];
    uint2 h;
    h.x = pack_h2(v.x, v.y); h.y = pack_h2(v.z, v.w);
    ((uint2*)(out + off))[i] = h;
}

// ===========================================================================
// fp16 GEMM: CTA 128x128, 8 warps (2x4), K-stage 64, dbl-buffered, ldmatrix.
// ===========================================================================
#define APAD2 36
#define TILE_U32 (128*APAD2)
#define TILE_B   (TILE_U32*4)          // 18432 bytes per tile
#define GEMM_SMEM (2*2*TILE_B)         // 73728 bytes (2 stages x {A,B})

__device__ __forceinline__ void gfill_h(
    uint32_t* smu, int stage,
    const uint32_t* __restrict__ A, const uint32_t* __restrict__ Bw,
    int row0, int col0, int k0u, int t)
{
    const int r = t >> 1, c0 = (t & 1) * 16;
    uint32_t* d = smu + stage * 2 * TILE_U32 + r * APAD2 + c0;
    const uint32_t* sA = A  + (size_t)(row0 + r) * 256 + k0u + c0;
    const uint32_t* sB = Bw + (size_t)(col0 + r) * 256 + k0u + c0;
#pragma unroll
    for (int u = 0; u < 4; u++) {
        ((uint4*)(d           ))[u] = ((const uint4*)sA)[u];
        ((uint4*)(d + TILE_U32))[u] = ((const uint4*)sB)[u];
    }
}

__device__ __forceinline__ void gemm_mainloop(
    uint32_t* smu, uint32_t smb,
    const uint32_t* __restrict__ A, const uint32_t* __restrict__ Bw,
    int row0, int col0, int t, float acc[4][4][4])
{
    const int lane = t & 31, wid = t >> 5;
    const int wm = wid & 1, wn = wid >> 1;
    const int lfoff = (((lane & 7) + ((lane >> 3) & 1) * 8) * APAD2 + (lane >> 4) * 4) * 4;

    gfill_h(smu, 0, A, Bw, row0, col0, 0, t);
    __syncthreads();

    for (int kt = 0; kt < 8; kt++) {
        if (kt < 7) gfill_h(smu, (kt + 1) & 1, A, Bw, row0, col0, (kt + 1) * 32, t);

        const uint32_t sb  = smb + (uint32_t)((kt & 1) * 2 * TILE_B);
        const uint32_t sbA = sb + (uint32_t)(wm * 64) * 144 + lfoff;
        const uint32_t sbB = sb + TILE_B + (uint32_t)(wn * 32) * 144 + lfoff;

#pragma unroll
        for (int ks = 0; ks < 4; ks++) {
            const uint32_t kb4 = ks * 32;
            uint32_t ah[4][4], bh[4][2];
#pragma unroll
            for (int mt = 0; mt < 4; mt++)
                LDSM_X4(ah[mt][0], ah[mt][1], ah[mt][2], ah[mt][3],
                        sbA + mt * (16*144) + kb4);
#pragma unroll
            for (int np = 0; np < 2; np++)
                LDSM_X4(bh[2*np][0], bh[2*np+1][0], bh[2*np][1], bh[2*np+1][1],
                        sbB + np * (16*144) + kb4);
#pragma unroll
            for (int mt = 0; mt < 4; mt++)
#pragma unroll
                for (int nt = 0; nt < 4; nt++)
                    MMA_FP16(acc[mt][nt][0],acc[mt][nt][1],acc[mt][nt][2],acc[mt][nt][3],
                             ah[mt][0],ah[mt][1],ah[mt][2],ah[mt][3], bh[nt][0],bh[nt][1]);
        }
        __syncthreads();
    }
}

// ---- fused QKV projection: grid (64, 12) ----
__global__ __launch_bounds__(256, 2) void gemm_qkv(
    const float* __restrict__ bq, const float* __restrict__ bk,
    const float* __restrict__ bv)
{
    extern __shared__ uint32_t smu[];
    const uint32_t smb = smem_u32(smu);
    const int t = threadIdx.x;
    const int lane = t & 31, wid = t >> 5;
    const int row0 = blockIdx.x * 128, col0 = blockIdx.y * 128;
    const int wm = wid & 1, wn = wid >> 1;
    const int g = lane >> 2, tig = lane & 3;

    float acc[4][4][4];
#pragma unroll
    for (int mt = 0; mt < 4; mt++)
#pragma unroll
        for (int nt = 0; nt < 4; nt++)
#pragma unroll
            for (int e = 0; e < 4; e++) acc[mt][nt][e] = 0.f;

    gemm_mainloop(smu, smb, g_x, g_w, row0, col0, t, acc);

    const int w = blockIdx.y >> 2;
    const float* bias = (w == 0) ? bq : (w == 1) ? bk : bv;
    uint32_t* oh = (w == 0) ? g_q : (w == 1) ? g_k : g_v;

#pragma unroll
    for (int mt = 0; mt < 4; mt++) {
#pragma unroll
        for (int nt = 0; nt < 4; nt++) {
            const int gc = col0 + wn*32 + nt*8 + tig*2;
            const int lc = gc & 511;
            const float b0 = bias[lc], b1 = bias[lc+1];
            const int h = lc >> 6, ucol = (lc >> 1) & 31;
            const int ra = row0 + wm*64 + mt*16 + g;
            const int rb = ra + 8;
            {
                const int bi = ra >> 10, ni = ra & 1023;
                oh[((size_t)(bi*Hh + h)*Nn + ni)*32 + ucol] =
                    pack_h2(acc[mt][nt][0] + b0, acc[mt][nt][1] + b1);
            }
            {
                const int bi = rb >> 10, ni = rb & 1023;
                oh[((size_t)(bi*Hh + h)*Nn + ni)*32 + ucol] =
                    pack_h2(acc[mt][nt][2] + b0, acc[mt][nt][3] + b1);
            }
        }
    }
}

// ---- output projection + residual: grid (64, 4) ----
__global__ __launch_bounds__(256, 2) void gemm_out(
    const float* __restrict__ bo, const float* __restrict__ resid)
{
    extern __shared__ uint32_t smu[];
    const uint32_t smb = smem_u32(smu);
    const int t = threadIdx.x;
    const int lane = t & 31, wid = t >> 5;
    const int row0 = blockIdx.x * 128, col0 = blockIdx.y * 128;
    const int wm = wid & 1, wn = wid >> 1;
    const int g = lane >> 2, tig = lane & 3;

    float acc[4][4][4];
#pragma unroll
    for (int mt = 0; mt < 4; mt++)
#pragma unroll
        for (int nt = 0; nt < 4; nt++)
#pragma unroll
            for (int e = 0; e < 4; e++) acc[mt][nt][e] = 0.f;

    gemm_mainloop(smu, smb, g_at, g_w + 3*512*256, row0, col0, t, acc);

#pragma unroll
    for (int mt = 0; mt < 4; mt++) {
#pragma unroll
        for (int nt = 0; nt < 4; nt++) {
            const int gc = col0 + wn*32 + nt*8 + tig*2;
            const float b0 = bo[gc], b1 = bo[gc+1];
            const int ra = row0 + wm*64 + mt*16 + g;
            const int rb = ra + 8;
            {
                const size_t off = (size_t)ra * Dd + gc;
                float2 x = *(const float2*)(resid + off);
                float2 r; r.x = acc[mt][nt][0] + b0 + x.x; r.y = acc[mt][nt][1] + b1 + x.y;
                *(float2*)(g_y + off) = r;
            }
            {
                const size_t off = (size_t)rb * Dd + gc;
                float2 x = *(const float2*)(resid + off);
                float2 r; r.x = acc[mt][nt][2] + b0 + x.x; r.y = acc[mt][nt][3] + b1 + x.y;
                *(float2*)(g_y + off) = r;
            }
        }
    }
}

// ===========================================================================
// fp16 tensor-core flash attention, fixed-max softmax.
// CTA = 128q x (b,h); 8 warps, warp = 16q x 128k.
// ===========================================================================
#define ASTRIDE 144
#define AT_TILE_U32 (128*36)
#define ATTN_SMEM (2*AT_TILE_U32*4)    // 36864 bytes (K, V)

__global__ __launch_bounds__(256, 1) void attn_kernel(const float* __restrict__ adj)
{
    extern __shared__ uint32_t smu[];
    const uint32_t smb = smem_u32(smu);
    const int t = threadIdx.x;
    const int lane = t & 31, wid = t >> 5;
    const int g = lane >> 2, tig = lane & 3;
    const int lm = lane >> 3, lr8 = lane & 7;
    const int q0 = blockIdx.x * 128;
    const int h  = blockIdx.y;
    const int b  = blockIdx.z;

    const size_t hbase = (size_t)(b*Hh + h) * Nn * 32;
    const uint32_t* Qg = g_q + hbase;
    const uint32_t* Kg = g_k + hbase;
    const uint32_t* Vg = g_v + hbase;

    const uint32_t smbK = smb;
    const uint32_t smbV = smb + AT_TILE_U32*4;

    const int lofK = ((lm >> 1)*8 + lr8) * ASTRIDE + (lm & 1) * 16;
    const int lofV = ((lm & 1)*8 + lr8) * ASTRIDE + (lm >> 1) * 16;

    const int rq  = q0 + wid*16 + g;
    const int rq8 = rq + 8;
    uint32_t qh[4][4];
#pragma unroll
    for (int ks = 0; ks < 4; ks++) {
        const int c = ks*8 + tig;
        qh[ks][0] = Qg[(size_t)rq *32 + c];     qh[ks][1] = Qg[(size_t)rq8*32 + c];
        qh[ks][2] = Qg[(size_t)rq *32 + c + 4]; qh[ks][3] = Qg[(size_t)rq8*32 + c + 4];
    }

    float o[8][4];
#pragma unroll
    for (int i = 0; i < 8; i++)
#pragma unroll
        for (int e = 0; e < 4; e++) o[i][e] = 0.f;
    float l0 = 0.f, l1 = 0.f;
    const float C = 0.125f * 1.44269504088896f;

    const int fr = t >> 1, fc = (t & 1) * 16;

    for (int kt = 0; kt < 8; kt++) {
        const int k0 = kt * 128;
        __syncthreads();
        {
            const size_t gsrc = (size_t)(k0 + fr) * 32 + fc;
            uint32_t* d = smu + fr*36 + fc;
#pragma unroll
            for (int u = 0; u < 4; u++) {
                ((uint4*)(d              ))[u] = ((const uint4*)(Kg + gsrc))[u];
                ((uint4*)(d + AT_TILE_U32))[u] = ((const uint4*)(Vg + gsrc))[u];
            }
        }
        __syncthreads();

        // ---- S = Q K^T (single fp16 pass) ----
        float sc[16][4];
#pragma unroll
        for (int i = 0; i < 16; i++)
#pragma unroll
            for (int e = 0; e < 4; e++) sc[i][e] = 0.f;

#pragma unroll
        for (int ks = 0; ks < 4; ks++) {
#pragma unroll
            for (int nfp = 0; nfp < 8; nfp++) {
                uint32_t kh0,kh1,kh2,kh3;
                LDSM_X4(kh0,kh1,kh2,kh3, smbK + lofK + nfp*2304 + ks*32);
                float* s0 = sc[2*nfp];
                float* s1 = sc[2*nfp+1];
                MMA_FP16(s0[0],s0[1],s0[2],s0[3], qh[ks][0],qh[ks][1],qh[ks][2],qh[ks][3], kh0,kh1);
                MMA_FP16(s1[0],s1[1],s1[2],s1[3], qh[ks][0],qh[ks][1],qh[ks][2],qh[ks][3], kh2,kh3);
            }
        }

        // ---- mask + exp (fixed max) + sum ----
        const float* arow0 = adj + ((size_t)b*Nn + rq )*Nn + k0 + 2*tig;
        const float* arow1 = adj + ((size_t)b*Nn + rq8)*Nn + k0 + 2*tig;
        float ps0 = 0.f, ps1 = 0.f;
#pragma unroll
        for (int nf = 0; nf < 16; nf++) {
            float2 a0 = *(const float2*)(arow0 + nf*8);
            float2 a1 = *(const float2*)(arow1 + nf*8);
            sc[nf][0] = ex2f(sc[nf][0] * C * a0.x);
            sc[nf][1] = ex2f(sc[nf][1] * C * a0.y);
            sc[nf][2] = ex2f(sc[nf][2] * C * a1.x);
            sc[nf][3] = ex2f(sc[nf][3] * C * a1.y);
            ps0 += sc[nf][0] + sc[nf][1];
            ps1 += sc[nf][2] + sc[nf][3];
        }
        l0 += ps0;
        l1 += ps1;

        // ---- O += P V (single fp16 pass) ----
#pragma unroll
        for (int j = 0; j < 8; j++) {
            const uint32_t ph0 = pack_h2(sc[2*j  ][0], sc[2*j  ][1]);
            const uint32_t ph1 = pack_h2(sc[2*j  ][2], sc[2*j  ][3]);
            const uint32_t ph2 = pack_h2(sc[2*j+1][0], sc[2*j+1][1]);
            const uint32_t ph3 = pack_h2(sc[2*j+1][2], sc[2*j+1][3]);
#pragma unroll
            for (int vx = 0; vx < 4; vx++) {
                uint32_t vh0,vh1,vh2,vh3;
                LDSM_X4_T(vh0,vh1,vh2,vh3, smbV + lofV + j*2304 + vx*32);
                float* o0 = o[2*vx];
                float* o1 = o[2*vx+1];
                MMA_FP16(o0[0],o0[1],o0[2],o0[3], ph0,ph1,ph2,ph3, vh0,vh1);
                MMA_FP16(o1[0],o1[1],o1[2],o1[3], ph0,ph1,ph2,ph3, vh2,vh3);
            }
        }
    }

    l0 += __shfl_xor_sync(0xffffffffu, l0, 1, 4);
    l0 += __shfl_xor_sync(0xffffffffu, l0, 2, 4);
    l1 += __shfl_xor_sync(0xffffffffu, l1, 1, 4);
    l1 += __shfl_xor_sync(0xffffffffu, l1, 2, 4);

    const float i0 = 1.0f / l0, i1 = 1.0f / l1;
    const size_t gr  = (size_t)b*Nn + rq;
    const size_t gr8 = (size_t)b*Nn + rq8;
#pragma unroll
    for (int dnf = 0; dnf < 8; dnf++) {
        const int ucol = h*32 + dnf*4 + tig;
        g_at[gr *256 + ucol] = pack_h2(o[dnf][0]*i0, o[dnf][1]*i0);
        g_at[gr8*256 + ucol] = pack_h2(o[dnf][2]*i1, o[dnf][3]*i1);
    }
}

// ---------------------------------------------------------------------------
// LayerNorm over last dim (512). One block (128 thr) per row.
// ---------------------------------------------------------------------------
__global__ __launch_bounds__(128) void ln_kernel(
    const float* __restrict__ gamma, const float* __restrict__ beta,
    float* __restrict__ out)
{
    const int row = blockIdx.x;
    const int t   = threadIdx.x;
    const float* y = g_y + (size_t)row * Dd;

    float4 v = *(const float4*)(y + t*4);
    float s  = v.x + v.y + v.z + v.w;
    float ss = v.x*v.x + v.y*v.y + v.z*v.z + v.w*v.w;
#pragma unroll
    for (int off = 16; off; off >>= 1) {
        s  += __shfl_xor_sync(0xffffffffu, s,  off);
        ss += __shfl_xor_sync(0xffffffffu, ss, off);
    }
    __shared__ float sbuf[8];
    const int w = t >> 5;
    if ((t & 31) == 0) { sbuf[w] = s; sbuf[4 + w] = ss; }
    __syncthreads();
    s  = sbuf[0] + sbuf[1] + sbuf[2] + sbuf[3];
    ss = sbuf[4] + sbuf[5] + sbuf[6] + sbuf[7];

    const float mean = s * (1.f/512.f);
    const float var  = ss * (1.f/512.f) - mean*mean;
    const float inv  = rsqrtf(var + 1e-5f);

    float4 g4 = *(const float4*)(gamma + t*4);
    float4 b4 = *(const float4*)(beta  + t*4);
    float4 r;
    r.x = (v.x - mean) * inv * g4.x + b4.x;
    r.y = (v.y - mean) * inv * g4.y + b4.y;
    r.z = (v.z - mean) * inv * g4.z + b4.z;
    r.w = (v.w - mean) * inv * g4.w + b4.w;
    *(float4*)(out + (size_t)row*Dd + t*4) = r;
}

// ---------------------------------------------------------------------------
extern "C" void kernel_launch(void* const* d_in, const int* in_sizes, int n_in,
                              void* d_out, int out_size)
{
    const float* X     = (const float*)d_in[0];
    const float* adj   = (const float*)d_in[1];
    const float* Wq    = (const float*)d_in[2];
    const float* bq    = (const float*)d_in[3];
    const float* Wk    = (const float*)d_in[4];
    const float* bk    = (const float*)d_in[5];
    const float* Wv    = (const float*)d_in[6];
    const float* bv    = (const float*)d_in[7];
    const float* Wo    = (const float*)d_in[8];
    const float* bo    = (const float*)d_in[9];
    const float* gamma = (const float*)d_in[10];
    const float* beta  = (const float*)d_in[11];

    uint32_t *x16, *w16;
    cudaGetSymbolAddress((void**)&x16, g_x);
    cudaGetSymbolAddress((void**)&w16, g_w);

    cudaFuncSetAttribute(gemm_qkv,
                         cudaFuncAttributeMaxDynamicSharedMemorySize, GEMM_SMEM);
    cudaFuncSetAttribute(gemm_out,
                         cudaFuncAttributeMaxDynamicSharedMemorySize, GEMM_SMEM);
    cudaFuncSetAttribute(attn_kernel,
                         cudaFuncAttributeMaxDynamicSharedMemorySize, ATTN_SMEM);

    cvt_kernel<<<Mrows*512/4/256, 256>>>(X, x16, Mrows*512/4);
    cvt4_kernel<<<dim3(256, 4), 256>>>(Wq, Wk, Wv, Wo, w16);

    gemm_qkv<<<dim3(Mrows/128, 12), 256, GEMM_SMEM>>>(bq, bk, bv);

    attn_kernel<<<dim3(Nn/128, Hh, Bsz), 256, ATTN_SMEM>>>(adj);

    gemm_out<<<dim3(Mrows/128, 4), 256, GEMM_SMEM>>>(bo, X);

    ln_kernel<<<Mrows, 128>>>(gamma, beta, (float*)d_out);
}

// round 9
// speedup vs baseline: 2.0867x; 1.0086x over previous
#include <cuda_runtime.h>
#include <cuda_fp16.h>
#include <math.h>
#include <stdint.h>

#define Bsz 8
#define Nn  1024
#define Dd  512
#define Hh  8
#define HD  64
#define Mrows (Bsz*Nn)

// ---------------- scratch (device globals) ----------------
__device__ uint32_t g_x[Mrows*256];              // X fp16 [row][256]
__device__ uint32_t g_w[4*512*256];              // weights fp16 [w][row][256]
__device__ uint32_t g_q[Bsz*Hh*Nn*32];           // [B,H,N][32]
__device__ uint32_t g_k[Bsz*Hh*Nn*32];
__device__ uint32_t g_v[Bsz*Hh*Nn*32];
__device__ uint32_t g_at[Mrows*256];             // attn out fp16 [row][256]
__device__ float    g_y[(size_t)Mrows*Dd];

// ---------------- helpers ----------------
__device__ __forceinline__ uint32_t smem_u32(const void* p) {
    uint32_t a;
    asm("{ .reg .u64 t; cvta.to.shared.u64 t, %1; cvt.u32.u64 %0, t; }" : "=r"(a) : "l"(p));
    return a;
}
__device__ __forceinline__ float ex2f(float x) {
    float r;
    asm("ex2.approx.ftz.f32 %0, %1;" : "=f"(r) : "f"(x));
    return r;
}
#define MMA_FP16(c0,c1,c2,c3, a0,a1,a2,a3, b0,b1) \
    asm volatile("mma.sync.aligned.m16n8k16.row.col.f32.f16.f16.f32 " \
        "{%0,%1,%2,%3},{%4,%5,%6,%7},{%8,%9},{%0,%1,%2,%3};" \
        : "+f"(c0),"+f"(c1),"+f"(c2),"+f"(c3) \
        : "r"(a0),"r"(a1),"r"(a2),"r"(a3),"r"(b0),"r"(b1))
#define LDSM_X4(r0,r1,r2,r3, a) \
    asm volatile("ldmatrix.sync.aligned.m8n8.x4.shared.b16 {%0,%1,%2,%3}, [%4];" \
        : "=r"(r0),"=r"(r1),"=r"(r2),"=r"(r3) : "r"(a))
#define LDSM_X4_T(r0,r1,r2,r3, a) \
    asm volatile("ldmatrix.sync.aligned.m8n8.x4.trans.shared.b16 {%0,%1,%2,%3}, [%4];" \
        : "=r"(r0),"=r"(r1),"=r"(r2),"=r"(r3) : "r"(a))
#define CP_ASYNC16(dst, src) \
    asm volatile("cp.async.cg.shared.global [%0], [%1], 16;" :: "r"(dst), "l"(src))
#define CP_COMMIT() asm volatile("cp.async.commit_group;" ::: "memory")
#define CP_WAIT(n)  asm volatile("cp.async.wait_group %0;" :: "n"(n) : "memory")

__device__ __forceinline__ uint32_t pack_h2(float x, float y) {
    __half2 p = __floats2half2_rn(x, y);
    return *(uint32_t*)&p;
}

// ---------------- fp32 -> fp16x2 converts ----------------
__global__ __launch_bounds__(256) void cvt_kernel(
    const float* __restrict__ in, uint32_t* __restrict__ out, int n4)
{
    int i = blockIdx.x * 256 + threadIdx.x;
    if (i < n4) {
        float4 v = ((const float4*)in)[i];
        uint2 h;
        h.x = pack_h2(v.x, v.y); h.y = pack_h2(v.z, v.w);
        ((uint2*)out)[i] = h;
    }
}

__global__ __launch_bounds__(256) void cvt4_kernel(
    const float* __restrict__ w0, const float* __restrict__ w1,
    const float* __restrict__ w2, const float* __restrict__ w3,
    uint32_t* __restrict__ out)
{
    const int wsel = blockIdx.y;
    const float* in = (wsel == 0) ? w0 : (wsel == 1) ? w1 : (wsel == 2) ? w2 : w3;
    const int i = blockIdx.x * 256 + threadIdx.x;
    const size_t off = (size_t)wsel * 512 * 256;
    float4 v = ((const float4*)in)[i];
    uint2 h;
    h.x = pack_h2(v.x, v.y); h.y = pack_h2(v.z, v.w);
    ((uint2*)(out + off))[i] = h;
}

// ===========================================================================
// fp16 GEMM (unchanged from R8): CTA 128x128, 8 warps, K-stage 64, dbl-buffer.
// ===========================================================================
#define APAD2 36
#define TILE_U32 (128*APAD2)
#define TILE_B   (TILE_U32*4)
#define GEMM_SMEM (2*2*TILE_B)         // 73728 bytes

__device__ __forceinline__ void gfill_h(
    uint32_t* smu, int stage,
    const uint32_t* __restrict__ A, const uint32_t* __restrict__ Bw,
    int row0, int col0, int k0u, int t)
{
    const int r = t >> 1, c0 = (t & 1) * 16;
    uint32_t* d = smu + stage * 2 * TILE_U32 + r * APAD2 + c0;
    const uint32_t* sA = A  + (size_t)(row0 + r) * 256 + k0u + c0;
    const uint32_t* sB = Bw + (size_t)(col0 + r) * 256 + k0u + c0;
#pragma unroll
    for (int u = 0; u < 4; u++) {
        ((uint4*)(d           ))[u] = ((const uint4*)sA)[u];
        ((uint4*)(d + TILE_U32))[u] = ((const uint4*)sB)[u];
    }
}

__device__ __forceinline__ void gemm_mainloop(
    uint32_t* smu, uint32_t smb,
    const uint32_t* __restrict__ A, const uint32_t* __restrict__ Bw,
    int row0, int col0, int t, float acc[4][4][4])
{
    const int lane = t & 31, wid = t >> 5;
    const int wm = wid & 1, wn = wid >> 1;
    const int lfoff = (((lane & 7) + ((lane >> 3) & 1) * 8) * APAD2 + (lane >> 4) * 4) * 4;

    gfill_h(smu, 0, A, Bw, row0, col0, 0, t);
    __syncthreads();

    for (int kt = 0; kt < 8; kt++) {
        if (kt < 7) gfill_h(smu, (kt + 1) & 1, A, Bw, row0, col0, (kt + 1) * 32, t);

        const uint32_t sb  = smb + (uint32_t)((kt & 1) * 2 * TILE_B);
        const uint32_t sbA = sb + (uint32_t)(wm * 64) * 144 + lfoff;
        const uint32_t sbB = sb + TILE_B + (uint32_t)(wn * 32) * 144 + lfoff;

#pragma unroll
        for (int ks = 0; ks < 4; ks++) {
            const uint32_t kb4 = ks * 32;
            uint32_t ah[4][4], bh[4][2];
#pragma unroll
            for (int mt = 0; mt < 4; mt++)
                LDSM_X4(ah[mt][0], ah[mt][1], ah[mt][2], ah[mt][3],
                        sbA + mt * (16*144) + kb4);
#pragma unroll
            for (int np = 0; np < 2; np++)
                LDSM_X4(bh[2*np][0], bh[2*np+1][0], bh[2*np][1], bh[2*np+1][1],
                        sbB + np * (16*144) + kb4);
#pragma unroll
            for (int mt = 0; mt < 4; mt++)
#pragma unroll
                for (int nt = 0; nt < 4; nt++)
                    MMA_FP16(acc[mt][nt][0],acc[mt][nt][1],acc[mt][nt][2],acc[mt][nt][3],
                             ah[mt][0],ah[mt][1],ah[mt][2],ah[mt][3], bh[nt][0],bh[nt][1]);
        }
        __syncthreads();
    }
}

__global__ __launch_bounds__(256, 2) void gemm_qkv(
    const float* __restrict__ bq, const float* __restrict__ bk,
    const float* __restrict__ bv)
{
    extern __shared__ uint32_t smu[];
    const uint32_t smb = smem_u32(smu);
    const int t = threadIdx.x;
    const int lane = t & 31, wid = t >> 5;
    const int row0 = blockIdx.x * 128, col0 = blockIdx.y * 128;
    const int wm = wid & 1, wn = wid >> 1;
    const int g = lane >> 2, tig = lane & 3;

    float acc[4][4][4];
#pragma unroll
    for (int mt = 0; mt < 4; mt++)
#pragma unroll
        for (int nt = 0; nt < 4; nt++)
#pragma unroll
            for (int e = 0; e < 4; e++) acc[mt][nt][e] = 0.f;

    gemm_mainloop(smu, smb, g_x, g_w, row0, col0, t, acc);

    const int w = blockIdx.y >> 2;
    const float* bias = (w == 0) ? bq : (w == 1) ? bk : bv;
    uint32_t* oh = (w == 0) ? g_q : (w == 1) ? g_k : g_v;

#pragma unroll
    for (int mt = 0; mt < 4; mt++) {
#pragma unroll
        for (int nt = 0; nt < 4; nt++) {
            const int gc = col0 + wn*32 + nt*8 + tig*2;
            const int lc = gc & 511;
            const float b0 = bias[lc], b1 = bias[lc+1];
            const int h = lc >> 6, ucol = (lc >> 1) & 31;
            const int ra = row0 + wm*64 + mt*16 + g;
            const int rb = ra + 8;
            {
                const int bi = ra >> 10, ni = ra & 1023;
                oh[((size_t)(bi*Hh + h)*Nn + ni)*32 + ucol] =
                    pack_h2(acc[mt][nt][0] + b0, acc[mt][nt][1] + b1);
            }
            {
                const int bi = rb >> 10, ni = rb & 1023;
                oh[((size_t)(bi*Hh + h)*Nn + ni)*32 + ucol] =
                    pack_h2(acc[mt][nt][2] + b0, acc[mt][nt][3] + b1);
            }
        }
    }
}

__global__ __launch_bounds__(256, 2) void gemm_out(
    const float* __restrict__ bo, const float* __restrict__ resid)
{
    extern __shared__ uint32_t smu[];
    const uint32_t smb = smem_u32(smu);
    const int t = threadIdx.x;
    const int lane = t & 31, wid = t >> 5;
    const int row0 = blockIdx.x * 128, col0 = blockIdx.y * 128;
    const int wm = wid & 1, wn = wid >> 1;
    const int g = lane >> 2, tig = lane & 3;

    float acc[4][4][4];
#pragma unroll
    for (int mt = 0; mt < 4; mt++)
#pragma unroll
        for (int nt = 0; nt < 4; nt++)
#pragma unroll
            for (int e = 0; e < 4; e++) acc[mt][nt][e] = 0.f;

    gemm_mainloop(smu, smb, g_at, g_w + 3*512*256, row0, col0, t, acc);

#pragma unroll
    for (int mt = 0; mt < 4; mt++) {
#pragma unroll
        for (int nt = 0; nt < 4; nt++) {
            const int gc = col0 + wn*32 + nt*8 + tig*2;
            const float b0 = bo[gc], b1 = bo[gc+1];
            const int ra = row0 + wm*64 + mt*16 + g;
            const int rb = ra + 8;
            {
                const size_t off = (size_t)ra * Dd + gc;
                float2 x = *(const float2*)(resid + off);
                float2 r; r.x = acc[mt][nt][0] + b0 + x.x; r.y = acc[mt][nt][1] + b1 + x.y;
                *(float2*)(g_y + off) = r;
            }
            {
                const size_t off = (size_t)rb * Dd + gc;
                float2 x = *(const float2*)(resid + off);
                float2 r; r.x = acc[mt][nt][2] + b0 + x.x; r.y = acc[mt][nt][3] + b1 + x.y;
                *(float2*)(g_y + off) = r;
            }
        }
    }
}

// ===========================================================================
// fp16 flash attention: cp.async double-buffered K/V, adj register prefetch.
// CTA = 128q x (b,h); 8 warps, warp = 16q x 128k.
// ===========================================================================
#define ASTRIDE 144
#define AT_TILE_U32 (128*36)
#define AT_TILE_BY  (AT_TILE_U32*4)
#define ATTN_SMEM (4*AT_TILE_U32*4)    // 73728: 2 stages x {K,V}

__global__ __launch_bounds__(256, 1) void attn_kernel(const float* __restrict__ adj)
{
    extern __shared__ uint32_t smu[];
    const uint32_t smb = smem_u32(smu);
    const int t = threadIdx.x;
    const int lane = t & 31, wid = t >> 5;
    const int g = lane >> 2, tig = lane & 3;
    const int lm = lane >> 3, lr8 = lane & 7;
    const int q0 = blockIdx.x * 128;
    const int h  = blockIdx.y;
    const int b  = blockIdx.z;

    const size_t hbase = (size_t)(b*Hh + h) * Nn * 32;
    const uint32_t* Qg = g_q + hbase;
    const uint32_t* Kg = g_k + hbase;
    const uint32_t* Vg = g_v + hbase;

    const int lofK = ((lm >> 1)*8 + lr8) * ASTRIDE + (lm & 1) * 16;
    const int lofV = ((lm & 1)*8 + lr8) * ASTRIDE + (lm >> 1) * 16;

    const int rq  = q0 + wid*16 + g;
    const int rq8 = rq + 8;
    uint32_t qh[4][4];
#pragma unroll
    for (int ks = 0; ks < 4; ks++) {
        const int c = ks*8 + tig;
        qh[ks][0] = Qg[(size_t)rq *32 + c];     qh[ks][1] = Qg[(size_t)rq8*32 + c];
        qh[ks][2] = Qg[(size_t)rq *32 + c + 4]; qh[ks][3] = Qg[(size_t)rq8*32 + c + 4];
    }

    float o[8][4];
#pragma unroll
    for (int i = 0; i < 8; i++)
#pragma unroll
        for (int e = 0; e < 4; e++) o[i][e] = 0.f;
    float l0 = 0.f, l1 = 0.f;
    const float C = 0.125f * 1.44269504088896f;

    const int fr = t >> 1, fc = (t & 1) * 16;
    const uint32_t fdst = smb + (uint32_t)(fr*36 + fc) * 4;

    // ---- preload stage 0 ----
    {
        const size_t gsrc = (size_t)fr * 32 + fc;
#pragma unroll
        for (int u = 0; u < 4; u++) {
            CP_ASYNC16(fdst + u*16,              Kg + gsrc + u*4);
            CP_ASYNC16(fdst + AT_TILE_BY + u*16, Vg + gsrc + u*4);
        }
        CP_COMMIT();
    }

    for (int kt = 0; kt < 8; kt++) {
        const int k0 = kt * 128;
        const uint32_t soff = (uint32_t)((kt & 1) * 2 * AT_TILE_BY);

        if (kt < 7) {
            const uint32_t d2 = fdst + (uint32_t)(((kt + 1) & 1) * 2 * AT_TILE_BY);
            const size_t gsrc = (size_t)(k0 + 128 + fr) * 32 + fc;
#pragma unroll
            for (int u = 0; u < 4; u++) {
                CP_ASYNC16(d2 + u*16,              Kg + gsrc + u*4);
                CP_ASYNC16(d2 + AT_TILE_BY + u*16, Vg + gsrc + u*4);
            }
            CP_COMMIT();
            CP_WAIT(1);
        } else {
            CP_WAIT(0);
        }
        __syncthreads();

        // ---- adjacency prefetch (independent of S; hides behind MMAs) ----
        const float* arow0 = adj + ((size_t)b*Nn + rq )*Nn + k0 + 2*tig;
        const float* arow1 = adj + ((size_t)b*Nn + rq8)*Nn + k0 + 2*tig;
        float2 aj0[16], aj1[16];
#pragma unroll
        for (int nf = 0; nf < 16; nf++) {
            aj0[nf] = *(const float2*)(arow0 + nf*8);
            aj1[nf] = *(const float2*)(arow1 + nf*8);
        }

        // ---- S = Q K^T ----
        const uint32_t smbK = smb + soff;
        const uint32_t smbV = smb + soff + AT_TILE_BY;
        float sc[16][4];
#pragma unroll
        for (int i = 0; i < 16; i++)
#pragma unroll
            for (int e = 0; e < 4; e++) sc[i][e] = 0.f;

#pragma unroll
        for (int ks = 0; ks < 4; ks++) {
#pragma unroll
            for (int nfp = 0; nfp < 8; nfp++) {
                uint32_t kh0,kh1,kh2,kh3;
                LDSM_X4(kh0,kh1,kh2,kh3, smbK + lofK + nfp*2304 + ks*32);
                float* s0 = sc[2*nfp];
                float* s1 = sc[2*nfp+1];
                MMA_FP16(s0[0],s0[1],s0[2],s0[3], qh[ks][0],qh[ks][1],qh[ks][2],qh[ks][3], kh0,kh1);
                MMA_FP16(s1[0],s1[1],s1[2],s1[3], qh[ks][0],qh[ks][1],qh[ks][2],qh[ks][3], kh2,kh3);
            }
        }

        // ---- mask + exp (fixed max) + sum ----
        float ps0 = 0.f, ps1 = 0.f;
#pragma unroll
        for (int nf = 0; nf < 16; nf++) {
            sc[nf][0] = ex2f(sc[nf][0] * C * aj0[nf].x);
            sc[nf][1] = ex2f(sc[nf][1] * C * aj0[nf].y);
            sc[nf][2] = ex2f(sc[nf][2] * C * aj1[nf].x);
            sc[nf][3] = ex2f(sc[nf][3] * C * aj1[nf].y);
            ps0 += sc[nf][0] + sc[nf][1];
            ps1 += sc[nf][2] + sc[nf][3];
        }
        l0 += ps0;
        l1 += ps1;

        // ---- O += P V ----
#pragma unroll
        for (int j = 0; j < 8; j++) {
            const uint32_t ph0 = pack_h2(sc[2*j  ][0], sc[2*j  ][1]);
            const uint32_t ph1 = pack_h2(sc[2*j  ][2], sc[2*j  ][3]);
            const uint32_t ph2 = pack_h2(sc[2*j+1][0], sc[2*j+1][1]);
            const uint32_t ph3 = pack_h2(sc[2*j+1][2], sc[2*j+1][3]);
#pragma unroll
            for (int vx = 0; vx < 4; vx++) {
                uint32_t vh0,vh1,vh2,vh3;
                LDSM_X4_T(vh0,vh1,vh2,vh3, smbV + lofV + j*2304 + vx*32);
                float* o0 = o[2*vx];
                float* o1 = o[2*vx+1];
                MMA_FP16(o0[0],o0[1],o0[2],o0[3], ph0,ph1,ph2,ph3, vh0,vh1);
                MMA_FP16(o1[0],o1[1],o1[2],o1[3], ph0,ph1,ph2,ph3, vh2,vh3);
            }
        }
        __syncthreads();   // all warps done with stage kt&1 before its refill
    }

    l0 += __shfl_xor_sync(0xffffffffu, l0, 1, 4);
    l0 += __shfl_xor_sync(0xffffffffu, l0, 2, 4);
    l1 += __shfl_xor_sync(0xffffffffu, l1, 1, 4);
    l1 += __shfl_xor_sync(0xffffffffu, l1, 2, 4);

    const float i0 = 1.0f / l0, i1 = 1.0f / l1;
    const size_t gr  = (size_t)b*Nn + rq;
    const size_t gr8 = (size_t)b*Nn + rq8;
#pragma unroll
    for (int dnf = 0; dnf < 8; dnf++) {
        const int ucol = h*32 + dnf*4 + tig;
        g_at[gr *256 + ucol] = pack_h2(o[dnf][0]*i0, o[dnf][1]*i0);
        g_at[gr8*256 + ucol] = pack_h2(o[dnf][2]*i1, o[dnf][3]*i1);
    }
}

// ---------------------------------------------------------------------------
// LayerNorm over last dim (512). One block (128 thr) per row.
// ---------------------------------------------------------------------------
__global__ __launch_bounds__(128) void ln_kernel(
    const float* __restrict__ gamma, const float* __restrict__ beta,
    float* __restrict__ out)
{
    const int row = blockIdx.x;
    const int t   = threadIdx.x;
    const float* y = g_y + (size_t)row * Dd;

    float4 v = *(const float4*)(y + t*4);
    float s  = v.x + v.y + v.z + v.w;
    float ss = v.x*v.x + v.y*v.y + v.z*v.z + v.w*v.w;
#pragma unroll
    for (int off = 16; off; off >>= 1) {
        s  += __shfl_xor_sync(0xffffffffu, s,  off);
        ss += __shfl_xor_sync(0xffffffffu, ss, off);
    }
    __shared__ float sbuf[8];
    const int w = t >> 5;
    if ((t & 31) == 0) { sbuf[w] = s; sbuf[4 + w] = ss; }
    __syncthreads();
    s  = sbuf[0] + sbuf[1] + sbuf[2] + sbuf[3];
    ss = sbuf[4] + sbuf[5] + sbuf[6] + sbuf[7];

    const float mean = s * (1.f/512.f);
    const float var  = ss * (1.f/512.f) - mean*mean;
    const float inv  = rsqrtf(var + 1e-5f);

    float4 g4 = *(const float4*)(gamma + t*4);
    float4 b4 = *(const float4*)(beta  + t*4);
    float4 r;
    r.x = (v.x - mean) * inv * g4.x + b4.x;
    r.y = (v.y - mean) * inv * g4.y + b4.y;
    r.z = (v.z - mean) * inv * g4.z + b4.z;
    r.w = (v.w - mean) * inv * g4.w + b4.w;
    *(float4*)(out + (size_t)row*Dd + t*4) = r;
}

// ---------------------------------------------------------------------------
extern "C" void kernel_launch(void* const* d_in, const int* in_sizes, int n_in,
                              void* d_out, int out_size)
{
    const float* X     = (const float*)d_in[0];
    const float* adj   = (const float*)d_in[1];
    const float* Wq    = (const float*)d_in[2];
    const float* bq    = (const float*)d_in[3];
    const float* Wk    = (const float*)d_in[4];
    const float* bk    = (const float*)d_in[5];
    const float* Wv    = (const float*)d_in[6];
    const float* bv    = (const float*)d_in[7];
    const float* Wo    = (const float*)d_in[8];
    const float* bo    = (const float*)d_in[9];
    const float* gamma = (const float*)d_in[10];
    const float* beta  = (const float*)d_in[11];

    uint32_t *x16, *w16;
    cudaGetSymbolAddress((void**)&x16, g_x);
    cudaGetSymbolAddress((void**)&w16, g_w);

    cudaFuncSetAttribute(gemm_qkv,
                         cudaFuncAttributeMaxDynamicSharedMemorySize, GEMM_SMEM);
    cudaFuncSetAttribute(gemm_out,
                         cudaFuncAttributeMaxDynamicSharedMemorySize, GEMM_SMEM);
    cudaFuncSetAttribute(attn_kernel,
                         cudaFuncAttributeMaxDynamicSharedMemorySize, ATTN_SMEM);

    cvt_kernel<<<Mrows*512/4/256, 256>>>(X, x16, Mrows*512/4);
    cvt4_kernel<<<dim3(256, 4), 256>>>(Wq, Wk, Wv, Wo, w16);

    gemm_qkv<<<dim3(Mrows/128, 12), 256, GEMM_SMEM>>>(bq, bk, bv);

    attn_kernel<<<dim3(Nn/128, Hh, Bsz), 256, ATTN_SMEM>>>(adj);

    gemm_out<<<dim3(Mrows/128, 4), 256, GEMM_SMEM>>>(bo, X);

    ln_kernel<<<Mrows, 128>>>(gamma, beta, (float*)d_out);
}

// round 10
// speedup vs baseline: 2.3227x; 1.1131x over previous
#include <cuda_runtime.h>
#include <cuda_fp16.h>
#include <math.h>
#include <stdint.h>

#define Bsz 8
#define Nn  1024
#define Dd  512
#define Hh  8
#define HD  64
#define Mrows (Bsz*Nn)

// ---------------- scratch (device globals) ----------------
__device__ uint32_t g_x[Mrows*256];              // X fp16 [row][256]
__device__ uint32_t g_w[4*512*256];              // weights fp16 [w][row][256]
__device__ uint32_t g_q[Bsz*Hh*Nn*32];           // [B,H,N][32]
__device__ uint32_t g_k[Bsz*Hh*Nn*32];
__device__ uint32_t g_v[Bsz*Hh*Nn*32];
__device__ uint32_t g_at[Mrows*256];             // attn out fp16 [row][256]
__device__ float    g_y[(size_t)Mrows*Dd];
__device__ uint32_t g_mask[Bsz*Nn*8*4];          // adjacency bitmask [b][r][kt][tig]

// ---------------- helpers ----------------
__device__ __forceinline__ uint32_t smem_u32(const void* p) {
    uint32_t a;
    asm("{ .reg .u64 t; cvta.to.shared.u64 t, %1; cvt.u32.u64 %0, t; }" : "=r"(a) : "l"(p));
    return a;
}
__device__ __forceinline__ float ex2f(float x) {
    float r;
    asm("ex2.approx.ftz.f32 %0, %1;" : "=f"(r) : "f"(x));
    return r;
}
#define MMA_FP16(c0,c1,c2,c3, a0,a1,a2,a3, b0,b1) \
    asm volatile("mma.sync.aligned.m16n8k16.row.col.f32.f16.f16.f32 " \
        "{%0,%1,%2,%3},{%4,%5,%6,%7},{%8,%9},{%0,%1,%2,%3};" \
        : "+f"(c0),"+f"(c1),"+f"(c2),"+f"(c3) \
        : "r"(a0),"r"(a1),"r"(a2),"r"(a3),"r"(b0),"r"(b1))
#define LDSM_X4(r0,r1,r2,r3, a) \
    asm volatile("ldmatrix.sync.aligned.m8n8.x4.shared.b16 {%0,%1,%2,%3}, [%4];" \
        : "=r"(r0),"=r"(r1),"=r"(r2),"=r"(r3) : "r"(a))
#define LDSM_X4_T(r0,r1,r2,r3, a) \
    asm volatile("ldmatrix.sync.aligned.m8n8.x4.trans.shared.b16 {%0,%1,%2,%3}, [%4];" \
        : "=r"(r0),"=r"(r1),"=r"(r2),"=r"(r3) : "r"(a))
#define CP_ASYNC16(dst, src) \
    asm volatile("cp.async.cg.shared.global [%0], [%1], 16;" :: "r"(dst), "l"(src))
#define CP_COMMIT() asm volatile("cp.async.commit_group;" ::: "memory")
#define CP_WAIT(n)  asm volatile("cp.async.wait_group %0;" :: "n"(n) : "memory")

__device__ __forceinline__ uint32_t pack_h2(float x, float y) {
    __half2 p = __floats2half2_rn(x, y);
    return *(uint32_t*)&p;
}

// ---------------- fp32 -> fp16x2 converts ----------------
__global__ __launch_bounds__(256) void cvt_kernel(
    const float* __restrict__ in, uint32_t* __restrict__ out, int n4)
{
    int i = blockIdx.x * 256 + threadIdx.x;
    if (i < n4) {
        float4 v = ((const float4*)in)[i];
        uint2 h;
        h.x = pack_h2(v.x, v.y); h.y = pack_h2(v.z, v.w);
        ((uint2*)out)[i] = h;
    }
}

__global__ __launch_bounds__(256) void cvt4_kernel(
    const float* __restrict__ w0, const float* __restrict__ w1,
    const float* __restrict__ w2, const float* __restrict__ w3,
    uint32_t* __restrict__ out)
{
    const int wsel = blockIdx.y;
    const float* in = (wsel == 0) ? w0 : (wsel == 1) ? w1 : (wsel == 2) ? w2 : w3;
    const int i = blockIdx.x * 256 + threadIdx.x;
    const size_t off = (size_t)wsel * 512 * 256;
    float4 v = ((const float4*)in)[i];
    uint2 h;
    h.x = pack_h2(v.x, v.y); h.y = pack_h2(v.z, v.w);
    ((uint2*)(out + off))[i] = h;
}

// ---------------- adjacency -> bitmask in thread-fragment layout ----------------
// bit (2*nf + p) of gmask[((b*Nn+r)*8+kt)*4+tig]  <->  adj[b][r][kt*128 + 8*nf + 2*tig + p]
__global__ __launch_bounds__(256) void mask_kernel(
    const float* __restrict__ adj, uint32_t* __restrict__ gmask)
{
    const int t = blockIdx.x * 256 + threadIdx.x;   // 262144 total
    const int tig = t & 3, kt = (t >> 2) & 7, r = (t >> 5) & 1023, b = t >> 15;
    const float* arow = adj + ((size_t)b*Nn + r)*Nn + kt*128 + 2*tig;
    uint32_t m = 0;
#pragma unroll
    for (int nf = 0; nf < 16; nf++) {
        float2 a = *(const float2*)(arow + nf*8);
        if (a.x != 0.f) m |= 1u << (2*nf);
        if (a.y != 0.f) m |= 1u << (2*nf + 1);
    }
    gmask[t] = m;
}

// ===========================================================================
// fp16 GEMM (unchanged): CTA 128x128, 8 warps, K-stage 64, dbl-buffer.
// ===========================================================================
#define APAD2 36
#define TILE_U32 (128*APAD2)
#define TILE_B   (TILE_U32*4)
#define GEMM_SMEM (2*2*TILE_B)         // 73728 bytes

__device__ __forceinline__ void gfill_h(
    uint32_t* smu, int stage,
    const uint32_t* __restrict__ A, const uint32_t* __restrict__ Bw,
    int row0, int col0, int k0u, int t)
{
    const int r = t >> 1, c0 = (t & 1) * 16;
    uint32_t* d = smu + stage * 2 * TILE_U32 + r * APAD2 + c0;
    const uint32_t* sA = A  + (size_t)(row0 + r) * 256 + k0u + c0;
    const uint32_t* sB = Bw + (size_t)(col0 + r) * 256 + k0u + c0;
#pragma unroll
    for (int u = 0; u < 4; u++) {
        ((uint4*)(d           ))[u] = ((const uint4*)sA)[u];
        ((uint4*)(d + TILE_U32))[u] = ((const uint4*)sB)[u];
    }
}

__device__ __forceinline__ void gemm_mainloop(
    uint32_t* smu, uint32_t smb,
    const uint32_t* __restrict__ A, const uint32_t* __restrict__ Bw,
    int row0, int col0, int t, float acc[4][4][4])
{
    const int lane = t & 31, wid = t >> 5;
    const int wm = wid & 1, wn = wid >> 1;
    const int lfoff = (((lane & 7) + ((lane >> 3) & 1) * 8) * APAD2 + (lane >> 4) * 4) * 4;

    gfill_h(smu, 0, A, Bw, row0, col0, 0, t);
    __syncthreads();

    for (int kt = 0; kt < 8; kt++) {
        if (kt < 7) gfill_h(smu, (kt + 1) & 1, A, Bw, row0, col0, (kt + 1) * 32, t);

        const uint32_t sb  = smb + (uint32_t)((kt & 1) * 2 * TILE_B);
        const uint32_t sbA = sb + (uint32_t)(wm * 64) * 144 + lfoff;
        const uint32_t sbB = sb + TILE_B + (uint32_t)(wn * 32) * 144 + lfoff;

#pragma unroll
        for (int ks = 0; ks < 4; ks++) {
            const uint32_t kb4 = ks * 32;
            uint32_t ah[4][4], bh[4][2];
#pragma unroll
            for (int mt = 0; mt < 4; mt++)
                LDSM_X4(ah[mt][0], ah[mt][1], ah[mt][2], ah[mt][3],
                        sbA + mt * (16*144) + kb4);
#pragma unroll
            for (int np = 0; np < 2; np++)
                LDSM_X4(bh[2*np][0], bh[2*np+1][0], bh[2*np][1], bh[2*np+1][1],
                        sbB + np * (16*144) + kb4);
#pragma unroll
            for (int mt = 0; mt < 4; mt++)
#pragma unroll
                for (int nt = 0; nt < 4; nt++)
                    MMA_FP16(acc[mt][nt][0],acc[mt][nt][1],acc[mt][nt][2],acc[mt][nt][3],
                             ah[mt][0],ah[mt][1],ah[mt][2],ah[mt][3], bh[nt][0],bh[nt][1]);
        }
        __syncthreads();
    }
}

__global__ __launch_bounds__(256, 2) void gemm_qkv(
    const float* __restrict__ bq, const float* __restrict__ bk,
    const float* __restrict__ bv)
{
    extern __shared__ uint32_t smu[];
    const uint32_t smb = smem_u32(smu);
    const int t = threadIdx.x;
    const int lane = t & 31, wid = t >> 5;
    const int row0 = blockIdx.x * 128, col0 = blockIdx.y * 128;
    const int wm = wid & 1, wn = wid >> 1;
    const int g = lane >> 2, tig = lane & 3;

    float acc[4][4][4];
#pragma unroll
    for (int mt = 0; mt < 4; mt++)
#pragma unroll
        for (int nt = 0; nt < 4; nt++)
#pragma unroll
            for (int e = 0; e < 4; e++) acc[mt][nt][e] = 0.f;

    gemm_mainloop(smu, smb, g_x, g_w, row0, col0, t, acc);

    const int w = blockIdx.y >> 2;
    const float* bias = (w == 0) ? bq : (w == 1) ? bk : bv;
    uint32_t* oh = (w == 0) ? g_q : (w == 1) ? g_k : g_v;

#pragma unroll
    for (int mt = 0; mt < 4; mt++) {
#pragma unroll
        for (int nt = 0; nt < 4; nt++) {
            const int gc = col0 + wn*32 + nt*8 + tig*2;
            const int lc = gc & 511;
            const float b0 = bias[lc], b1 = bias[lc+1];
            const int h = lc >> 6, ucol = (lc >> 1) & 31;
            const int ra = row0 + wm*64 + mt*16 + g;
            const int rb = ra + 8;
            {
                const int bi = ra >> 10, ni = ra & 1023;
                oh[((size_t)(bi*Hh + h)*Nn + ni)*32 + ucol] =
                    pack_h2(acc[mt][nt][0] + b0, acc[mt][nt][1] + b1);
            }
            {
                const int bi = rb >> 10, ni = rb & 1023;
                oh[((size_t)(bi*Hh + h)*Nn + ni)*32 + ucol] =
                    pack_h2(acc[mt][nt][2] + b0, acc[mt][nt][3] + b1);
            }
        }
    }
}

__global__ __launch_bounds__(256, 2) void gemm_out(
    const float* __restrict__ bo, const float* __restrict__ resid)
{
    extern __shared__ uint32_t smu[];
    const uint32_t smb = smem_u32(smu);
    const int t = threadIdx.x;
    const int lane = t & 31, wid = t >> 5;
    const int row0 = blockIdx.x * 128, col0 = blockIdx.y * 128;
    const int wm = wid & 1, wn = wid >> 1;
    const int g = lane >> 2, tig = lane & 3;

    float acc[4][4][4];
#pragma unroll
    for (int mt = 0; mt < 4; mt++)
#pragma unroll
        for (int nt = 0; nt < 4; nt++)
#pragma unroll
            for (int e = 0; e < 4; e++) acc[mt][nt][e] = 0.f;

    gemm_mainloop(smu, smb, g_at, g_w + 3*512*256, row0, col0, t, acc);

#pragma unroll
    for (int mt = 0; mt < 4; mt++) {
#pragma unroll
        for (int nt = 0; nt < 4; nt++) {
            const int gc = col0 + wn*32 + nt*8 + tig*2;
            const float b0 = bo[gc], b1 = bo[gc+1];
            const int ra = row0 + wm*64 + mt*16 + g;
            const int rb = ra + 8;
            {
                const size_t off = (size_t)ra * Dd + gc;
                float2 x = *(const float2*)(resid + off);
                float2 r; r.x = acc[mt][nt][0] + b0 + x.x; r.y = acc[mt][nt][1] + b1 + x.y;
                *(float2*)(g_y + off) = r;
            }
            {
                const size_t off = (size_t)rb * Dd + gc;
                float2 x = *(const float2*)(resid + off);
                float2 r; r.x = acc[mt][nt][2] + b0 + x.x; r.y = acc[mt][nt][3] + b1 + x.y;
                *(float2*)(g_y + off) = r;
            }
        }
    }
}

// ===========================================================================
// fp16 flash attention, 2 CTAs/SM: interleaved S->exp->PV per 16-key block,
// bitmask adjacency, cp.async double-buffered K/V.
// ===========================================================================
#define ASTRIDE 144
#define AT_TILE_U32 (128*36)
#define AT_TILE_BY  (AT_TILE_U32*4)
#define ATTN_SMEM (4*AT_TILE_U32*4)    // 73728: 2 stages x {K,V}

__global__ __launch_bounds__(256, 2) void attn_kernel()
{
    extern __shared__ uint32_t smu[];
    const uint32_t smb = smem_u32(smu);
    const int t = threadIdx.x;
    const int lane = t & 31, wid = t >> 5;
    const int g = lane >> 2, tig = lane & 3;
    const int lm = lane >> 3, lr8 = lane & 7;
    const int q0 = blockIdx.x * 128;
    const int h  = blockIdx.y;
    const int b  = blockIdx.z;

    const size_t hbase = (size_t)(b*Hh + h) * Nn * 32;
    const uint32_t* Qg = g_q + hbase;
    const uint32_t* Kg = g_k + hbase;
    const uint32_t* Vg = g_v + hbase;

    const int lofK = ((lm >> 1)*8 + lr8) * ASTRIDE + (lm & 1) * 16;
    const int lofV = ((lm & 1)*8 + lr8) * ASTRIDE + (lm >> 1) * 16;

    const int rq  = q0 + wid*16 + g;
    const int rq8 = rq + 8;
    uint32_t qh[4][4];
#pragma unroll
    for (int ks = 0; ks < 4; ks++) {
        const int c = ks*8 + tig;
        qh[ks][0] = Qg[(size_t)rq *32 + c];     qh[ks][1] = Qg[(size_t)rq8*32 + c];
        qh[ks][2] = Qg[(size_t)rq *32 + c + 4]; qh[ks][3] = Qg[(size_t)rq8*32 + c + 4];
    }

    float o[8][4];
#pragma unroll
    for (int i = 0; i < 8; i++)
#pragma unroll
        for (int e = 0; e < 4; e++) o[i][e] = 0.f;
    float l0 = 0.f, l1 = 0.f;
    const float C = 0.125f * 1.44269504088896f;

    const int fr = t >> 1, fc = (t & 1) * 16;
    const uint32_t fdst = smb + (uint32_t)(fr*36 + fc) * 4;

    const uint32_t* mrow0 = g_mask + ((size_t)(b*Nn + rq )*8)*4 + tig;
    const uint32_t* mrow1 = g_mask + ((size_t)(b*Nn + rq8)*8)*4 + tig;

    // ---- preload stage 0 ----
    {
        const size_t gsrc = (size_t)fr * 32 + fc;
#pragma unroll
        for (int u = 0; u < 4; u++) {
            CP_ASYNC16(fdst + u*16,              Kg + gsrc + u*4);
            CP_ASYNC16(fdst + AT_TILE_BY + u*16, Vg + gsrc + u*4);
        }
        CP_COMMIT();
    }

    for (int kt = 0; kt < 8; kt++) {
        const int k0 = kt * 128;
        const uint32_t soff = (uint32_t)((kt & 1) * 2 * AT_TILE_BY);

        if (kt < 7) {
            const uint32_t d2 = fdst + (uint32_t)(((kt + 1) & 1) * 2 * AT_TILE_BY);
            const size_t gsrc = (size_t)(k0 + 128 + fr) * 32 + fc;
#pragma unroll
            for (int u = 0; u < 4; u++) {
                CP_ASYNC16(d2 + u*16,              Kg + gsrc + u*4);
                CP_ASYNC16(d2 + AT_TILE_BY + u*16, Vg + gsrc + u*4);
            }
            CP_COMMIT();
            CP_WAIT(1);
        } else {
            CP_WAIT(0);
        }
        __syncthreads();

        const uint32_t m0 = mrow0[kt*4];
        const uint32_t m1 = mrow1[kt*4];
        const uint32_t smbK = smb + soff;
        const uint32_t smbV = smb + soff + AT_TILE_BY;

#pragma unroll
        for (int j = 0; j < 8; j++) {
            // ---- S for this 16-key block ----
            float s0[4] = {0.f, 0.f, 0.f, 0.f};
            float s1[4] = {0.f, 0.f, 0.f, 0.f};
#pragma unroll
            for (int ks = 0; ks < 4; ks++) {
                uint32_t kh0,kh1,kh2,kh3;
                LDSM_X4(kh0,kh1,kh2,kh3, smbK + lofK + j*2304 + ks*32);
                MMA_FP16(s0[0],s0[1],s0[2],s0[3], qh[ks][0],qh[ks][1],qh[ks][2],qh[ks][3], kh0,kh1);
                MMA_FP16(s1[0],s1[1],s1[2],s1[3], qh[ks][0],qh[ks][1],qh[ks][2],qh[ks][3], kh2,kh3);
            }

            // ---- mask (bit-select) + exp + sum ----
            const float e00 = ex2f(((m0 >> (4*j  )) & 1) ? s0[0]*C : 0.f);
            const float e01 = ex2f(((m0 >> (4*j+1)) & 1) ? s0[1]*C : 0.f);
            const float e02 = ex2f(((m1 >> (4*j  )) & 1) ? s0[2]*C : 0.f);
            const float e03 = ex2f(((m1 >> (4*j+1)) & 1) ? s0[3]*C : 0.f);
            const float e10 = ex2f(((m0 >> (4*j+2)) & 1) ? s1[0]*C : 0.f);
            const float e11 = ex2f(((m0 >> (4*j+3)) & 1) ? s1[1]*C : 0.f);
            const float e12 = ex2f(((m1 >> (4*j+2)) & 1) ? s1[2]*C : 0.f);
            const float e13 = ex2f(((m1 >> (4*j+3)) & 1) ? s1[3]*C : 0.f);
            l0 += e00 + e01 + e10 + e11;
            l1 += e02 + e03 + e12 + e13;

            const uint32_t ph0 = pack_h2(e00, e01);
            const uint32_t ph1 = pack_h2(e02, e03);
            const uint32_t ph2 = pack_h2(e10, e11);
            const uint32_t ph3 = pack_h2(e12, e13);

            // ---- PV for this key block ----
#pragma unroll
            for (int vx = 0; vx < 4; vx++) {
                uint32_t vh0,vh1,vh2,vh3;
                LDSM_X4_T(vh0,vh1,vh2,vh3, smbV + lofV + j*2304 + vx*32);
                float* o0 = o[2*vx];
                float* o1 = o[2*vx+1];
                MMA_FP16(o0[0],o0[1],o0[2],o0[3], ph0,ph1,ph2,ph3, vh0,vh1);
                MMA_FP16(o1[0],o1[1],o1[2],o1[3], ph0,ph1,ph2,ph3, vh2,vh3);
            }
        }
        __syncthreads();
    }

    l0 += __shfl_xor_sync(0xffffffffu, l0, 1, 4);
    l0 += __shfl_xor_sync(0xffffffffu, l0, 2, 4);
    l1 += __shfl_xor_sync(0xffffffffu, l1, 1, 4);
    l1 += __shfl_xor_sync(0xffffffffu, l1, 2, 4);

    const float i0 = 1.0f / l0, i1 = 1.0f / l1;
    const size_t gr  = (size_t)b*Nn + rq;
    const size_t gr8 = (size_t)b*Nn + rq8;
#pragma unroll
    for (int dnf = 0; dnf < 8; dnf++) {
        const int ucol = h*32 + dnf*4 + tig;
        g_at[gr *256 + ucol] = pack_h2(o[dnf][0]*i0, o[dnf][1]*i0);
        g_at[gr8*256 + ucol] = pack_h2(o[dnf][2]*i1, o[dnf][3]*i1);
    }
}

// ---------------------------------------------------------------------------
// LayerNorm over last dim (512). One block (128 thr) per row.
// ---------------------------------------------------------------------------
__global__ __launch_bounds__(128) void ln_kernel(
    const float* __restrict__ gamma, const float* __restrict__ beta,
    float* __restrict__ out)
{
    const int row = blockIdx.x;
    const int t   = threadIdx.x;
    const float* y = g_y + (size_t)row * Dd;

    float4 v = *(const float4*)(y + t*4);
    float s  = v.x + v.y + v.z + v.w;
    float ss = v.x*v.x + v.y*v.y + v.z*v.z + v.w*v.w;
#pragma unroll
    for (int off = 16; off; off >>= 1) {
        s  += __shfl_xor_sync(0xffffffffu, s,  off);
        ss += __shfl_xor_sync(0xffffffffu, ss, off);
    }
    __shared__ float sbuf[8];
    const int w = t >> 5;
    if ((t & 31) == 0) { sbuf[w] = s; sbuf[4 + w] = ss; }
    __syncthreads();
    s  = sbuf[0] + sbuf[1] + sbuf[2] + sbuf[3];
    ss = sbuf[4] + sbuf[5] + sbuf[6] + sbuf[7];

    const float mean = s * (1.f/512.f);
    const float var  = ss * (1.f/512.f) - mean*mean;
    const float inv  = rsqrtf(var + 1e-5f);

    float4 g4 = *(const float4*)(gamma + t*4);
    float4 b4 = *(const float4*)(beta  + t*4);
    float4 r;
    r.x = (v.x - mean) * inv * g4.x + b4.x;
    r.y = (v.y - mean) * inv * g4.y + b4.y;
    r.z = (v.z - mean) * inv * g4.z + b4.z;
    r.w = (v.w - mean) * inv * g4.w + b4.w;
    *(float4*)(out + (size_t)row*Dd + t*4) = r;
}

// ---------------------------------------------------------------------------
extern "C" void kernel_launch(void* const* d_in, const int* in_sizes, int n_in,
                              void* d_out, int out_size)
{
    const float* X     = (const float*)d_in[0];
    const float* adj   = (const float*)d_in[1];
    const float* Wq    = (const float*)d_in[2];
    const float* bq    = (const float*)d_in[3];
    const float* Wk    = (const float*)d_in[4];
    const float* bk    = (const float*)d_in[5];
    const float* Wv    = (const float*)d_in[6];
    const float* bv    = (const float*)d_in[7];
    const float* Wo    = (const float*)d_in[8];
    const float* bo    = (const float*)d_in[9];
    const float* gamma = (const float*)d_in[10];
    const float* beta  = (const float*)d_in[11];

    uint32_t *x16, *w16, *mk;
    cudaGetSymbolAddress((void**)&x16, g_x);
    cudaGetSymbolAddress((void**)&w16, g_w);
    cudaGetSymbolAddress((void**)&mk,  g_mask);

    cudaFuncSetAttribute(gemm_qkv,
                         cudaFuncAttributeMaxDynamicSharedMemorySize, GEMM_SMEM);
    cudaFuncSetAttribute(gemm_out,
                         cudaFuncAttributeMaxDynamicSharedMemorySize, GEMM_SMEM);
    cudaFuncSetAttribute(attn_kernel,
                         cudaFuncAttributeMaxDynamicSharedMemorySize, ATTN_SMEM);

    cvt_kernel<<<Mrows*512/4/256, 256>>>(X, x16, Mrows*512/4);
    cvt4_kernel<<<dim3(256, 4), 256>>>(Wq, Wk, Wv, Wo, w16);
    mask_kernel<<<Bsz*Nn*8*4/256, 256>>>(adj, mk);

    gemm_qkv<<<dim3(Mrows/128, 12), 256, GEMM_SMEM>>>(bq, bk, bv);

    attn_kernel<<<dim3(Nn/128, Hh, Bsz), 256, ATTN_SMEM>>>();

    gemm_out<<<dim3(Mrows/128, 4), 256, GEMM_SMEM>>>(bo, X);

    ln_kernel<<<Mrows, 128>>>(gamma, beta, (float*)d_out);
}